// round 1
// baseline (speedup 1.0000x reference)
#include <cuda_runtime.h>
#include <cstdint>

#define Wd 256
#define Hd 256
#define HW (Wd*Hd)
#define KP 64
#define NSTEP 64
#define DT (1.0f/256.0f)
#define INV_DT 256.0f
#define VOLR 256.0f

// Transposed voxel template: [k][z][y][x] -> float4(c0,c1,c2,c3). 4 MB static.
__device__ float4 g_vox[KP * 16 * 16 * 16];

__global__ void transpose_vox_kernel(const float* __restrict__ rgba) {
    int v = blockIdx.x * blockDim.x + threadIdx.x;   // 0 .. KP*4096-1
    if (v >= KP * 4096) return;
    int k = v >> 12;
    int off = v & 4095;
    const float* b = rgba + (size_t)k * 16384 + off; // [k][c][4096], channel stride 4096
    g_vox[v] = make_float4(b[0], b[4096], b[8192], b[12288]);
}

__global__ void __launch_bounds__(256, 1)
march_kernel(const float* __restrict__ raypos, const float* __restrict__ raydir,
             const float* __restrict__ tminmax, const float* __restrict__ primpos,
             const float* __restrict__ primrot, const float* __restrict__ primscale,
             float* __restrict__ out, int out_size)
{
    __shared__ float wlo[8][3], whi[8][3];
    __shared__ float sbmin[3], sbmax[3];
    __shared__ unsigned sball[2];
    __shared__ int snact;
    __shared__ float sprim[KP][16];   // [0..2]=pos, [3..11]=rot row-major, [12..14]=scale
    __shared__ int skid[KP];

    const int tid = threadIdx.x;
    const int tx = tid & 15, ty = tid >> 4;
    const int w = blockIdx.x * 16 + tx;
    const int h = blockIdx.y * 16 + ty;
    const int r = h * Wd + w;

    const float ox = raypos[r*3+0], oy = raypos[r*3+1], oz = raypos[r*3+2];
    const float dx = raydir[r*3+0], dy = raydir[r*3+1], dz = raydir[r*3+2];
    const float tmn = tminmax[r*2+0], tmx = tminmax[r*2+1];

    // ---- block segment AABB (min/max of both endpoints over all rays) ----
    float e0x = ox + tmn*dx, e0y = oy + tmn*dy, e0z = oz + tmn*dz;
    float e1x = ox + tmx*dx, e1y = oy + tmx*dy, e1z = oz + tmx*dz;
    float lx_ = fminf(e0x, e1x), ly_ = fminf(e0y, e1y), lz_ = fminf(e0z, e1z);
    float hx_ = fmaxf(e0x, e1x), hy_ = fmaxf(e0y, e1y), hz_ = fmaxf(e0z, e1z);
    #pragma unroll
    for (int off = 16; off; off >>= 1) {
        lx_ = fminf(lx_, __shfl_xor_sync(0xFFFFFFFFu, lx_, off));
        ly_ = fminf(ly_, __shfl_xor_sync(0xFFFFFFFFu, ly_, off));
        lz_ = fminf(lz_, __shfl_xor_sync(0xFFFFFFFFu, lz_, off));
        hx_ = fmaxf(hx_, __shfl_xor_sync(0xFFFFFFFFu, hx_, off));
        hy_ = fmaxf(hy_, __shfl_xor_sync(0xFFFFFFFFu, hy_, off));
        hz_ = fmaxf(hz_, __shfl_xor_sync(0xFFFFFFFFu, hz_, off));
    }
    int warp = tid >> 5;
    if ((tid & 31) == 0) {
        wlo[warp][0] = lx_; wlo[warp][1] = ly_; wlo[warp][2] = lz_;
        whi[warp][0] = hx_; whi[warp][1] = hy_; whi[warp][2] = hz_;
    }
    __syncthreads();
    if (tid == 0) {
        const float M = 1e-3f;
        float a0 = wlo[0][0], a1 = wlo[0][1], a2 = wlo[0][2];
        float b0 = whi[0][0], b1 = whi[0][1], b2 = whi[0][2];
        #pragma unroll
        for (int i = 1; i < 8; i++) {
            a0 = fminf(a0, wlo[i][0]); a1 = fminf(a1, wlo[i][1]); a2 = fminf(a2, wlo[i][2]);
            b0 = fmaxf(b0, whi[i][0]); b1 = fmaxf(b1, whi[i][1]); b2 = fmaxf(b2, whi[i][2]);
        }
        sbmin[0] = a0 - M; sbmin[1] = a1 - M; sbmin[2] = a2 - M;
        sbmax[0] = b0 + M; sbmax[1] = b1 + M; sbmax[2] = b2 + M;
    }
    __syncthreads();

    // ---- cull prims vs block AABB; deterministic ordered compaction ----
    bool act = false;
    float px=0, py=0, pz=0, sx=0, sy=0, sz=0;
    float rot[9];
    if (tid < KP) {
        int k = tid;
        px = primpos[k*3+0] * (1.0f/VOLR);
        py = primpos[k*3+1] * (1.0f/VOLR);
        pz = primpos[k*3+2] * (1.0f/VOLR);
        sx = primscale[k*3+0]; sy = primscale[k*3+1]; sz = primscale[k*3+2];
        #pragma unroll
        for (int i = 0; i < 9; i++) rot[i] = primrot[k*9+i];
        float isx = 1.0f/sx, isy = 1.0f/sy, isz = 1.0f/sz;
        // extent_i = sum_j |rot[i][j]| / scale[j]
        float ex = fabsf(rot[0])*isx + fabsf(rot[1])*isy + fabsf(rot[2])*isz;
        float ey = fabsf(rot[3])*isx + fabsf(rot[4])*isy + fabsf(rot[5])*isz;
        float ez = fabsf(rot[6])*isx + fabsf(rot[7])*isy + fabsf(rot[8])*isz;
        act = (px - ex <= sbmax[0]) && (px + ex >= sbmin[0]) &&
              (py - ey <= sbmax[1]) && (py + ey >= sbmin[1]) &&
              (pz - ez <= sbmax[2]) && (pz + ez >= sbmin[2]);
    }
    unsigned ball = __ballot_sync(0xFFFFFFFFu, act);
    if ((tid & 31) == 0 && warp < 2) sball[warp] = ball;
    __syncthreads();
    if (tid < KP && act) {
        unsigned lanemask = (1u << (tid & 31)) - 1u;
        int idx = (tid < 32) ? __popc(sball[0] & lanemask)
                             : __popc(sball[0]) + __popc(sball[1] & lanemask);
        skid[idx] = tid;
        sprim[idx][0] = px; sprim[idx][1] = py; sprim[idx][2] = pz;
        #pragma unroll
        for (int i = 0; i < 9; i++) sprim[idx][3+i] = rot[i];
        sprim[idx][12] = sx; sprim[idx][13] = sy; sprim[idx][14] = sz;
    }
    if (tid == 0) snact = __popc(sball[0]) + __popc(sball[1]);
    __syncthreads();
    const int nact = snact;

    // ---- per-ray: step interval for each surviving prim ----
    unsigned ivl[KP];
    int myn = 0, rlo = NSTEP, rhi = -1;
    for (int kk = 0; kk < nact; kk++) {
        const float* P = sprim[kk];
        float rx = ox - P[0], ry = oy - P[1], rz = oz - P[2];
        float ax = (P[3]*rx + P[6]*ry + P[9] *rz) * P[12];
        float ay = (P[4]*rx + P[7]*ry + P[10]*rz) * P[13];
        float az = (P[5]*rx + P[8]*ry + P[11]*rz) * P[14];
        float bx = (P[3]*dx + P[6]*dy + P[9] *dz) * P[12];
        float by = (P[4]*dx + P[7]*dy + P[10]*dz) * P[13];
        float bz = (P[5]*dx + P[8]*dy + P[11]*dz) * P[14];
        float t0 = tmn, t1 = tmx;
        #pragma unroll
        for (int ax3 = 0; ax3 < 3; ax3++) {
            float a = (ax3 == 0) ? ax : (ax3 == 1) ? ay : az;
            float b = (ax3 == 0) ? bx : (ax3 == 1) ? by : bz;
            if (fabsf(b) > 1e-9f) {
                float inv = 1.0f / b;
                float l = (-1.0f - a) * inv;
                float hgh = (1.0f - a) * inv;
                t0 = fmaxf(t0, fminf(l, hgh));
                t1 = fminf(t1, fmaxf(l, hgh));
            } else if (fabsf(a) >= 1.0f) {
                t1 = -1e30f;
            }
        }
        // widen by 0.01 step; exact inside-check at sample time keeps correctness
        int ilo = (int)ceilf((t0 - tmn) * INV_DT - 0.51f);
        int ihi = (int)floorf((t1 - tmn) * INV_DT - 0.49f);
        ilo = max(ilo, 0); ihi = min(ihi, NSTEP - 1);
        if (ihi >= ilo) {
            ivl[myn++] = (unsigned)kk | ((unsigned)ilo << 8) | ((unsigned)ihi << 16);
            rlo = min(rlo, ilo);
            rhi = max(rhi, ihi);
        }
    }

    // ---- march ----
    float crx = 0.f, cry = 0.f, crz = 0.f, alpha = 0.f;
    for (int i = rlo; i <= rhi; i++) {
        float t = tmn + ((float)i + 0.5f) * DT;
        float posx = ox + t*dx, posy = oy + t*dy, posz = oz + t*dz;
        float s0 = 0.f, s1 = 0.f, s2 = 0.f, s3 = 0.f;
        for (int m = 0; m < myn; m++) {
            unsigned e = ivl[m];
            int ilo = (e >> 8) & 255, ihi = (e >> 16) & 255;
            if (i < ilo || i > ihi) continue;
            int kk = e & 255;
            const float* P = sprim[kk];
            float rx = posx - P[0], ry = posy - P[1], rz = posz - P[2];
            float lx = (P[3]*rx + P[6]*ry + P[9] *rz) * P[12];
            float ly = (P[4]*rx + P[7]*ry + P[10]*rz) * P[13];
            float lz = (P[5]*rx + P[8]*ry + P[11]*rz) * P[14];
            if (fabsf(lx) < 1.0f && fabsf(ly) < 1.0f && fabsf(lz) < 1.0f) {
                int k = skid[kk];
                float gx = fminf(fmaxf((lx + 1.0f) * 7.5f, 0.0f), 15.0f - 1e-5f);
                float gy = fminf(fmaxf((ly + 1.0f) * 7.5f, 0.0f), 15.0f - 1e-5f);
                float gz = fminf(fmaxf((lz + 1.0f) * 7.5f, 0.0f), 15.0f - 1e-5f);
                int x0 = min((int)gx, 14);
                int y0 = min((int)gy, 14);
                int z0 = min((int)gz, 14);
                float fx = gx - (float)x0, fy = gy - (float)y0, fz = gz - (float)z0;
                const float4* base = g_vox + (((k*16 + z0)*16 + y0)*16 + x0);
                float4 v000 = base[0],   v001 = base[1];
                float4 v010 = base[16],  v011 = base[17];
                float4 v100 = base[256], v101 = base[257];
                float4 v110 = base[272], v111 = base[273];
                float w0z = 1.f - fz, w0y = 1.f - fy, w0x = 1.f - fx;
                float w00 = w0z*w0y, w01 = w0z*fy, w10 = fz*w0y, w11 = fz*fy;
                float w000 = w00*w0x, w001 = w00*fx;
                float w010 = w01*w0x, w011 = w01*fx;
                float w100 = w10*w0x, w101 = w10*fx;
                float w110 = w11*w0x, w111 = w11*fx;
                s0 = fmaf(v000.x,w000,fmaf(v001.x,w001,fmaf(v010.x,w010,fmaf(v011.x,w011,
                     fmaf(v100.x,w100,fmaf(v101.x,w101,fmaf(v110.x,w110,fmaf(v111.x,w111,s0))))))));
                s1 = fmaf(v000.y,w000,fmaf(v001.y,w001,fmaf(v010.y,w010,fmaf(v011.y,w011,
                     fmaf(v100.y,w100,fmaf(v101.y,w101,fmaf(v110.y,w110,fmaf(v111.y,w111,s1))))))));
                s2 = fmaf(v000.z,w000,fmaf(v001.z,w001,fmaf(v010.z,w010,fmaf(v011.z,w011,
                     fmaf(v100.z,w100,fmaf(v101.z,w101,fmaf(v110.z,w110,fmaf(v111.z,w111,s2))))))));
                s3 = fmaf(v000.w,w000,fmaf(v001.w,w001,fmaf(v010.w,w010,fmaf(v011.w,w011,
                     fmaf(v100.w,w100,fmaf(v101.w,w101,fmaf(v110.w,w110,fmaf(v111.w,w111,s3))))))));
            }
        }
        float contrib = fminf(1.0f, alpha + s3 * DT) - alpha;
        if (!(t < tmx)) contrib = 0.0f;
        crx = fmaf(s0, contrib, crx);
        cry = fmaf(s1, contrib, cry);
        crz = fmaf(s2, contrib, crz);
        alpha += contrib;
    }

    // ---- outputs: rayrgb (3,H,W), rayalpha (1,H,W), rayrgba (4,H,W) concatenated ----
    if (out_size >= 8 * HW) {
        out[0*HW + r] = crx; out[1*HW + r] = cry; out[2*HW + r] = crz;
        out[3*HW + r] = alpha;
        out[4*HW + r] = crx; out[5*HW + r] = cry; out[6*HW + r] = crz;
        out[7*HW + r] = alpha;
    } else {
        out[0*HW + r] = crx; out[1*HW + r] = cry; out[2*HW + r] = crz;
        out[3*HW + r] = alpha;
    }
}

extern "C" void kernel_launch(void* const* d_in, const int* in_sizes, int n_in,
                              void* d_out, int out_size) {
    const float* raypos    = (const float*)d_in[0];
    const float* raydir    = (const float*)d_in[1];
    const float* tminmax   = (const float*)d_in[2];
    const float* primpos   = (const float*)d_in[3];
    const float* primrot   = (const float*)d_in[4];
    const float* primscale = (const float*)d_in[5];
    const float* primrgba  = (const float*)d_in[6];
    float* out = (float*)d_out;

    transpose_vox_kernel<<<(KP*4096 + 255)/256, 256>>>(primrgba);
    dim3 grid(Wd/16, Hd/16);
    march_kernel<<<grid, 256>>>(raypos, raydir, tminmax, primpos, primrot,
                                primscale, out, out_size);
}

// round 2
// speedup vs baseline: 21.2100x; 21.2100x over previous
#include <cuda_runtime.h>
#include <cstdint>

#define Wd 256
#define Hd 256
#define HW (Wd*Hd)
#define KP 64
#define NSTEP 64
#define DT (1.0f/256.0f)
#define INV_DT 256.0f
#define VOLR 256.0f

// Transposed voxel template: [k][z][y][x] -> float4(c0..c3). 4 MB.
__device__ float4 g_vox[KP * 4096];
// Per-(step, ray) accumulated sample: [step][ray]. 64 MB.
__device__ float4 g_s[NSTEP * HW];

__global__ void zero_s_kernel() {
    int i = blockIdx.x * blockDim.x + threadIdx.x;   // exactly NSTEP*HW threads
    g_s[i] = make_float4(0.f, 0.f, 0.f, 0.f);
}

__global__ void transpose_vox_kernel(const float* __restrict__ rgba) {
    int v = blockIdx.x * blockDim.x + threadIdx.x;   // 0 .. KP*4096-1
    if (v >= KP * 4096) return;
    int k = v >> 12;
    int off = v & 4095;
    const float* b = rgba + (size_t)k * 16384 + off; // [k][c][4096]
    g_vox[v] = make_float4(b[0], b[4096], b[8192], b[12288]);
}

// One block = one 8x8 ray subtile of one prim's screen bbox.
// grid = (MAX_SUBTILES, KP); block = 64 threads.
__global__ void __launch_bounds__(64)
splat_kernel(const float* __restrict__ raypos, const float* __restrict__ raydir,
             const float* __restrict__ tminmax, const float* __restrict__ primpos,
             const float* __restrict__ primrot, const float* __restrict__ primscale)
{
    const int k = blockIdx.y;

    // prim params (broadcast loads)
    const float px = primpos[k*3+0] * (1.0f/VOLR);
    const float py = primpos[k*3+1] * (1.0f/VOLR);
    const float pz = primpos[k*3+2] * (1.0f/VOLR);
    const float sx = primscale[k*3+0];
    const float sy = primscale[k*3+1];
    const float sz = primscale[k*3+2];
    float rot[9];
    #pragma unroll
    for (int i = 0; i < 9; i++) rot[i] = primrot[k*9+i];

    // world-axis-aligned half extents of the |local|<1 box
    const float isx = 1.0f/sx, isy = 1.0f/sy, isz = 1.0f/sz;
    const float ex = fabsf(rot[0])*isx + fabsf(rot[1])*isy + fabsf(rot[2])*isz;
    const float ey = fabsf(rot[3])*isx + fabsf(rot[4])*isy + fabsf(rot[5])*isz;

    // screen bbox (pixel x = -1 + 2*w/255) with safety margin
    int wlo = (int)floorf((px - ex + 1.0f) * 127.5f) - 1;
    int whi = (int)ceilf ((px + ex + 1.0f) * 127.5f) + 1;
    int hlo = (int)floorf((py - ey + 1.0f) * 127.5f) - 1;
    int hhi = (int)ceilf ((py + ey + 1.0f) * 127.5f) + 1;
    wlo = max(wlo, 0); whi = min(whi, Wd-1);
    hlo = max(hlo, 0); hhi = min(hhi, Hd-1);
    if (whi < wlo || hhi < hlo) return;

    const int bw = ((whi - wlo) >> 3) + 1;
    const int bh = ((hhi - hlo) >> 3) + 1;
    const int bidx = blockIdx.x;
    if (bidx >= bw * bh) return;

    const int w = wlo + (bidx % bw) * 8 + (threadIdx.x & 7);
    const int h = hlo + (bidx / bw) * 8 + (threadIdx.x >> 3);
    if (w > whi || h > hhi) return;
    const int r = h * Wd + w;

    const float ox = raypos[r*3+0], oy = raypos[r*3+1], oz = raypos[r*3+2];
    const float dx = raydir[r*3+0], dy = raydir[r*3+1], dz = raydir[r*3+2];
    const float tmn = tminmax[r*2+0], tmx = tminmax[r*2+1];

    // local(t) = a + t*b   (local_j = sum_i rot[i][j]*rel_i * scale_j)
    const float rx = ox - px, ry = oy - py, rz = oz - pz;
    const float ax = (rot[0]*rx + rot[3]*ry + rot[6]*rz) * sx;
    const float ay = (rot[1]*rx + rot[4]*ry + rot[7]*rz) * sy;
    const float az = (rot[2]*rx + rot[5]*ry + rot[8]*rz) * sz;
    const float bx = (rot[0]*dx + rot[3]*dy + rot[6]*dz) * sx;
    const float by = (rot[1]*dx + rot[4]*dy + rot[7]*dz) * sy;
    const float bz = (rot[2]*dx + rot[5]*dy + rot[8]*dz) * sz;

    // slab clip |a + t b| < 1 on all three axes
    float t0 = tmn, t1 = tmx;
    #pragma unroll
    for (int ax3 = 0; ax3 < 3; ax3++) {
        float a = (ax3 == 0) ? ax : (ax3 == 1) ? ay : az;
        float b = (ax3 == 0) ? bx : (ax3 == 1) ? by : bz;
        if (fabsf(b) > 1e-9f) {
            float inv = 1.0f / b;
            float l = (-1.0f - a) * inv;
            float hgh = (1.0f - a) * inv;
            t0 = fmaxf(t0, fminf(l, hgh));
            t1 = fminf(t1, fmaxf(l, hgh));
        } else if (fabsf(a) >= 1.0f) {
            t1 = -1e30f;
        }
    }
    int ilo = (int)ceilf((t0 - tmn) * INV_DT - 0.51f);
    int ihi = (int)floorf((t1 - tmn) * INV_DT - 0.49f);
    ilo = max(ilo, 0); ihi = min(ihi, NSTEP - 1);
    if (ihi < ilo) return;

    const float4* vk = g_vox + k * 4096;

    for (int i = ilo; i <= ihi; i++) {
        float t = tmn + ((float)i + 0.5f) * DT;
        float lx = fmaf(t, bx, ax);
        float ly = fmaf(t, by, ay);
        float lz = fmaf(t, bz, az);
        if (!(fabsf(lx) < 1.0f && fabsf(ly) < 1.0f && fabsf(lz) < 1.0f)) continue;

        float gx = fminf(fmaxf((lx + 1.0f) * 7.5f, 0.0f), 15.0f - 1e-5f);
        float gy = fminf(fmaxf((ly + 1.0f) * 7.5f, 0.0f), 15.0f - 1e-5f);
        float gz = fminf(fmaxf((lz + 1.0f) * 7.5f, 0.0f), 15.0f - 1e-5f);
        int x0 = min((int)gx, 14);
        int y0 = min((int)gy, 14);
        int z0 = min((int)gz, 14);
        float fx = gx - (float)x0, fy = gy - (float)y0, fz = gz - (float)z0;

        const float4* base = vk + ((z0*16 + y0)*16 + x0);
        float4 v000 = base[0],   v001 = base[1];
        float4 v010 = base[16],  v011 = base[17];
        float4 v100 = base[256], v101 = base[257];
        float4 v110 = base[272], v111 = base[273];

        float w0z = 1.f - fz, w0y = 1.f - fy, w0x = 1.f - fx;
        float w00 = w0z*w0y, w01 = w0z*fy, w10 = fz*w0y, w11 = fz*fy;
        float w000 = w00*w0x, w001 = w00*fx;
        float w010 = w01*w0x, w011 = w01*fx;
        float w100 = w10*w0x, w101 = w10*fx;
        float w110 = w11*w0x, w111 = w11*fx;

        float s0 = fmaf(v000.x,w000,fmaf(v001.x,w001,fmaf(v010.x,w010,fmaf(v011.x,w011,
                   fmaf(v100.x,w100,fmaf(v101.x,w101,fmaf(v110.x,w110,v111.x*w111)))))));
        float s1 = fmaf(v000.y,w000,fmaf(v001.y,w001,fmaf(v010.y,w010,fmaf(v011.y,w011,
                   fmaf(v100.y,w100,fmaf(v101.y,w101,fmaf(v110.y,w110,v111.y*w111)))))));
        float s2 = fmaf(v000.z,w000,fmaf(v001.z,w001,fmaf(v010.z,w010,fmaf(v011.z,w011,
                   fmaf(v100.z,w100,fmaf(v101.z,w101,fmaf(v110.z,w110,v111.z*w111)))))));
        float s3 = fmaf(v000.w,w000,fmaf(v001.w,w001,fmaf(v010.w,w010,fmaf(v011.w,w011,
                   fmaf(v100.w,w100,fmaf(v101.w,w101,fmaf(v110.w,w110,v111.w*w111)))))));

        float* dst = (float*)&g_s[i * HW + r];
        atomicAdd(dst + 0, s0);
        atomicAdd(dst + 1, s1);
        atomicAdd(dst + 2, s2);
        atomicAdd(dst + 3, s3);
    }
}

__global__ void __launch_bounds__(256)
composite_kernel(const float* __restrict__ tminmax, float* __restrict__ out, int out_size)
{
    const int r = blockIdx.x * 256 + threadIdx.x;
    const float tmn = tminmax[r*2+0], tmx = tminmax[r*2+1];

    float crx = 0.f, cry = 0.f, crz = 0.f, alpha = 0.f;
    #pragma unroll 8
    for (int i = 0; i < NSTEP; i++) {
        float4 s = g_s[i * HW + r];
        float t = tmn + ((float)i + 0.5f) * DT;
        float contrib = fminf(1.0f, fmaf(s.w, DT, alpha)) - alpha;
        if (!(t < tmx)) contrib = 0.0f;
        crx = fmaf(s.x, contrib, crx);
        cry = fmaf(s.y, contrib, cry);
        crz = fmaf(s.z, contrib, crz);
        alpha += contrib;
    }

    if (out_size >= 8 * HW) {
        out[0*HW + r] = crx; out[1*HW + r] = cry; out[2*HW + r] = crz;
        out[3*HW + r] = alpha;
        out[4*HW + r] = crx; out[5*HW + r] = cry; out[6*HW + r] = crz;
        out[7*HW + r] = alpha;
    } else {
        out[0*HW + r] = crx; out[1*HW + r] = cry; out[2*HW + r] = crz;
        out[3*HW + r] = alpha;
    }
}

extern "C" void kernel_launch(void* const* d_in, const int* in_sizes, int n_in,
                              void* d_out, int out_size) {
    const float* raypos    = (const float*)d_in[0];
    const float* raydir    = (const float*)d_in[1];
    const float* tminmax   = (const float*)d_in[2];
    const float* primpos   = (const float*)d_in[3];
    const float* primrot   = (const float*)d_in[4];
    const float* primscale = (const float*)d_in[5];
    const float* primrgba  = (const float*)d_in[6];
    float* out = (float*)d_out;

    zero_s_kernel<<<(NSTEP*HW)/256, 256>>>();
    transpose_vox_kernel<<<(KP*4096 + 255)/256, 256>>>(primrgba);
    dim3 sgrid(121, KP);
    splat_kernel<<<sgrid, 64>>>(raypos, raydir, tminmax, primpos, primrot, primscale);
    composite_kernel<<<HW/256, 256>>>(tminmax, out, out_size);
}

// round 4
// speedup vs baseline: 25.4466x; 1.1997x over previous
#include <cuda_runtime.h>
#include <cstdint>

#define Wd 256
#define Hd 256
#define HW (Wd*Hd)
#define KP 64
#define NSTEP 64
#define DT (1.0f/256.0f)
#define INV_DT 256.0f
#define VOLR 256.0f

// Transposed voxel template: [k][z][y][x] -> float4(c0..c3). 4 MB.
__device__ float4 g_vox[KP * 4096];
// Per-(step, ray) accumulated sample: [step][ray]. 64 MB (only bbox region used).
__device__ float4 g_s[NSTEP * HW];
// Union screen bbox of all prims: wlo, whi, hlo, hhi
__device__ int g_bb[4];

// ---------------------------------------------------------------- bbox ----
__global__ void bbox_kernel(const float* __restrict__ primpos,
                            const float* __restrict__ primrot,
                            const float* __restrict__ primscale)
{
    __shared__ int s4[4][2];   // [coord][warp]
    const int k = threadIdx.x; // 64 threads, one per prim
    const float px = primpos[k*3+0] * (1.0f/VOLR);
    const float py = primpos[k*3+1] * (1.0f/VOLR);
    float rot[9];
    #pragma unroll
    for (int i = 0; i < 9; i++) rot[i] = primrot[k*9+i];
    const float isx = 1.0f/primscale[k*3+0];
    const float isy = 1.0f/primscale[k*3+1];
    const float isz = 1.0f/primscale[k*3+2];
    const float ex = fabsf(rot[0])*isx + fabsf(rot[1])*isy + fabsf(rot[2])*isz;
    const float ey = fabsf(rot[3])*isx + fabsf(rot[4])*isy + fabsf(rot[5])*isz;

    int wlo = (int)floorf((px - ex + 1.0f) * 127.5f) - 1;
    int whi = (int)ceilf ((px + ex + 1.0f) * 127.5f) + 1;
    int hlo = (int)floorf((py - ey + 1.0f) * 127.5f) - 1;
    int hhi = (int)ceilf ((py + ey + 1.0f) * 127.5f) + 1;

    #pragma unroll
    for (int off = 16; off; off >>= 1) {
        wlo = min(wlo, __shfl_xor_sync(0xFFFFFFFFu, wlo, off));
        hlo = min(hlo, __shfl_xor_sync(0xFFFFFFFFu, hlo, off));
        whi = max(whi, __shfl_xor_sync(0xFFFFFFFFu, whi, off));
        hhi = max(hhi, __shfl_xor_sync(0xFFFFFFFFu, hhi, off));
    }
    const int warp = threadIdx.x >> 5;
    if ((threadIdx.x & 31) == 0) {
        s4[0][warp] = wlo; s4[1][warp] = whi;
        s4[2][warp] = hlo; s4[3][warp] = hhi;
    }
    __syncthreads();
    if (threadIdx.x == 0) {
        g_bb[0] = max(min(s4[0][0], s4[0][1]), 0);
        g_bb[1] = min(max(s4[1][0], s4[1][1]), Wd-1);
        g_bb[2] = max(min(s4[2][0], s4[2][1]), 0);
        g_bb[3] = min(max(s4[3][0], s4[3][1]), Hd-1);
    }
}

// ---------------------------------------------------------------- zero ----
__global__ void zero_s_kernel() {
    int i = blockIdx.x * blockDim.x + threadIdx.x;   // NSTEP*HW threads
    int r = i & (HW - 1);
    int w = r & (Wd - 1), h = r >> 8;
    if (w < g_bb[0] || w > g_bb[1] || h < g_bb[2] || h > g_bb[3]) return;
    g_s[i] = make_float4(0.f, 0.f, 0.f, 0.f);
}

// ----------------------------------------------------------- transpose ----
__global__ void transpose_vox_kernel(const float* __restrict__ rgba) {
    int v = blockIdx.x * blockDim.x + threadIdx.x;   // 0 .. KP*4096-1
    if (v >= KP * 4096) return;
    int k = v >> 12;
    int off = v & 4095;
    const float* b = rgba + (size_t)k * 16384 + off; // [k][c][4096]
    g_vox[v] = make_float4(b[0], b[4096], b[8192], b[12288]);
}

// --------------------------------------------------------------- splat ----
// One block = one 8x8 ray subtile of one prim's screen bbox.
__global__ void __launch_bounds__(64)
splat_kernel(const float* __restrict__ raypos, const float* __restrict__ raydir,
             const float* __restrict__ tminmax, const float* __restrict__ primpos,
             const float* __restrict__ primrot, const float* __restrict__ primscale)
{
    const int k = blockIdx.y;

    const float px = primpos[k*3+0] * (1.0f/VOLR);
    const float py = primpos[k*3+1] * (1.0f/VOLR);
    const float pz = primpos[k*3+2] * (1.0f/VOLR);
    const float sx = primscale[k*3+0];
    const float sy = primscale[k*3+1];
    const float sz = primscale[k*3+2];
    float rot[9];
    #pragma unroll
    for (int i = 0; i < 9; i++) rot[i] = primrot[k*9+i];

    const float isx = 1.0f/sx, isy = 1.0f/sy, isz = 1.0f/sz;
    const float ex = fabsf(rot[0])*isx + fabsf(rot[1])*isy + fabsf(rot[2])*isz;
    const float ey = fabsf(rot[3])*isx + fabsf(rot[4])*isy + fabsf(rot[5])*isz;

    int wlo = (int)floorf((px - ex + 1.0f) * 127.5f) - 1;
    int whi = (int)ceilf ((px + ex + 1.0f) * 127.5f) + 1;
    int hlo = (int)floorf((py - ey + 1.0f) * 127.5f) - 1;
    int hhi = (int)ceilf ((py + ey + 1.0f) * 127.5f) + 1;
    wlo = max(wlo, 0); whi = min(whi, Wd-1);
    hlo = max(hlo, 0); hhi = min(hhi, Hd-1);
    if (whi < wlo || hhi < hlo) return;

    const int bw = ((whi - wlo) >> 3) + 1;
    const int bh = ((hhi - hlo) >> 3) + 1;
    const int bidx = blockIdx.x;
    if (bidx >= bw * bh) return;

    const int w = wlo + (bidx % bw) * 8 + (threadIdx.x & 7);
    const int h = hlo + (bidx / bw) * 8 + (threadIdx.x >> 3);
    if (w > whi || h > hhi) return;
    const int r = h * Wd + w;

    const float ox = raypos[r*3+0], oy = raypos[r*3+1], oz = raypos[r*3+2];
    const float dx = raydir[r*3+0], dy = raydir[r*3+1], dz = raydir[r*3+2];
    const float tmn = tminmax[r*2+0], tmx = tminmax[r*2+1];

    // local(t) = a + t*b
    const float rx = ox - px, ry = oy - py, rz = oz - pz;
    const float ax = (rot[0]*rx + rot[3]*ry + rot[6]*rz) * sx;
    const float ay = (rot[1]*rx + rot[4]*ry + rot[7]*rz) * sy;
    const float az = (rot[2]*rx + rot[5]*ry + rot[8]*rz) * sz;
    const float bx = (rot[0]*dx + rot[3]*dy + rot[6]*dz) * sx;
    const float by = (rot[1]*dx + rot[4]*dy + rot[7]*dz) * sy;
    const float bz = (rot[2]*dx + rot[5]*dy + rot[8]*dz) * sz;

    float t0 = tmn, t1 = tmx;
    #pragma unroll
    for (int ax3 = 0; ax3 < 3; ax3++) {
        float a = (ax3 == 0) ? ax : (ax3 == 1) ? ay : az;
        float b = (ax3 == 0) ? bx : (ax3 == 1) ? by : bz;
        if (fabsf(b) > 1e-9f) {
            float inv = 1.0f / b;
            float l = (-1.0f - a) * inv;
            float hgh = (1.0f - a) * inv;
            t0 = fmaxf(t0, fminf(l, hgh));
            t1 = fminf(t1, fmaxf(l, hgh));
        } else if (fabsf(a) >= 1.0f) {
            t1 = -1e30f;
        }
    }
    int ilo = (int)ceilf((t0 - tmn) * INV_DT - 0.51f);
    int ihi = (int)floorf((t1 - tmn) * INV_DT - 0.49f);
    ilo = max(ilo, 0); ihi = min(ihi, NSTEP - 1);
    if (ihi < ilo) return;

    const float4* vk = g_vox + k * 4096;

    for (int i = ilo; i <= ihi; i++) {
        float t = tmn + ((float)i + 0.5f) * DT;
        float lx = fmaf(t, bx, ax);
        float ly = fmaf(t, by, ay);
        float lz = fmaf(t, bz, az);
        if (!(fabsf(lx) < 1.0f && fabsf(ly) < 1.0f && fabsf(lz) < 1.0f)) continue;

        float gx = fminf(fmaxf((lx + 1.0f) * 7.5f, 0.0f), 15.0f - 1e-5f);
        float gy = fminf(fmaxf((ly + 1.0f) * 7.5f, 0.0f), 15.0f - 1e-5f);
        float gz = fminf(fmaxf((lz + 1.0f) * 7.5f, 0.0f), 15.0f - 1e-5f);
        int x0 = min((int)gx, 14);
        int y0 = min((int)gy, 14);
        int z0 = min((int)gz, 14);
        float fx = gx - (float)x0, fy = gy - (float)y0, fz = gz - (float)z0;

        const float4* base = vk + ((z0*16 + y0)*16 + x0);
        float4 v000 = base[0],   v001 = base[1];
        float4 v010 = base[16],  v011 = base[17];
        float4 v100 = base[256], v101 = base[257];
        float4 v110 = base[272], v111 = base[273];

        float w0z = 1.f - fz, w0y = 1.f - fy, w0x = 1.f - fx;
        float w00 = w0z*w0y, w01 = w0z*fy, w10 = fz*w0y, w11 = fz*fy;
        float w000 = w00*w0x, w001 = w00*fx;
        float w010 = w01*w0x, w011 = w01*fx;
        float w100 = w10*w0x, w101 = w10*fx;
        float w110 = w11*w0x, w111 = w11*fx;

        float s0 = fmaf(v000.x,w000,fmaf(v001.x,w001,fmaf(v010.x,w010,fmaf(v011.x,w011,
                   fmaf(v100.x,w100,fmaf(v101.x,w101,fmaf(v110.x,w110,v111.x*w111)))))));
        float s1 = fmaf(v000.y,w000,fmaf(v001.y,w001,fmaf(v010.y,w010,fmaf(v011.y,w011,
                   fmaf(v100.y,w100,fmaf(v101.y,w101,fmaf(v110.y,w110,v111.y*w111)))))));
        float s2 = fmaf(v000.z,w000,fmaf(v001.z,w001,fmaf(v010.z,w010,fmaf(v011.z,w011,
                   fmaf(v100.z,w100,fmaf(v101.z,w101,fmaf(v110.z,w110,v111.z*w111)))))));
        float s3 = fmaf(v000.w,w000,fmaf(v001.w,w001,fmaf(v010.w,w010,fmaf(v011.w,w011,
                   fmaf(v100.w,w100,fmaf(v101.w,w101,fmaf(v110.w,w110,v111.w*w111)))))));

        // single vectorized reduction (sm_90+): 1 instruction instead of 4
        float* dst = (float*)&g_s[i * HW + r];
        asm volatile("red.global.add.v4.f32 [%0], {%1, %2, %3, %4};"
                     :: "l"(dst), "f"(s0), "f"(s1), "f"(s2), "f"(s3) : "memory");
    }
}

// ----------------------------------------------------------- composite ----
__global__ void __launch_bounds__(256)
composite_kernel(const float* __restrict__ tminmax, float* __restrict__ out, int out_size)
{
    const int r = blockIdx.x * 256 + threadIdx.x;
    const int w = r & (Wd - 1), h = r >> 8;

    float crx = 0.f, cry = 0.f, crz = 0.f, alpha = 0.f;
    if (!(w < g_bb[0] || w > g_bb[1] || h < g_bb[2] || h > g_bb[3])) {
        const float tmn = tminmax[r*2+0], tmx = tminmax[r*2+1];
        #pragma unroll 8
        for (int i = 0; i < NSTEP; i++) {
            float4 s = g_s[i * HW + r];
            float t = tmn + ((float)i + 0.5f) * DT;
            float contrib = fminf(1.0f, fmaf(s.w, DT, alpha)) - alpha;
            if (!(t < tmx)) contrib = 0.0f;
            crx = fmaf(s.x, contrib, crx);
            cry = fmaf(s.y, contrib, cry);
            crz = fmaf(s.z, contrib, crz);
            alpha += contrib;
        }
    }

    if (out_size >= 8 * HW) {
        out[0*HW + r] = crx; out[1*HW + r] = cry; out[2*HW + r] = crz;
        out[3*HW + r] = alpha;
        out[4*HW + r] = crx; out[5*HW + r] = cry; out[6*HW + r] = crz;
        out[7*HW + r] = alpha;
    } else {
        out[0*HW + r] = crx; out[1*HW + r] = cry; out[2*HW + r] = crz;
        out[3*HW + r] = alpha;
    }
}

extern "C" void kernel_launch(void* const* d_in, const int* in_sizes, int n_in,
                              void* d_out, int out_size) {
    const float* raypos    = (const float*)d_in[0];
    const float* raydir    = (const float*)d_in[1];
    const float* tminmax   = (const float*)d_in[2];
    const float* primpos   = (const float*)d_in[3];
    const float* primrot   = (const float*)d_in[4];
    const float* primscale = (const float*)d_in[5];
    const float* primrgba  = (const float*)d_in[6];
    float* out = (float*)d_out;

    bbox_kernel<<<1, 64>>>(primpos, primrot, primscale);
    transpose_vox_kernel<<<(KP*4096 + 255)/256, 256>>>(primrgba);
    zero_s_kernel<<<(NSTEP*HW)/256, 256>>>();
    dim3 sgrid(121, KP);
    splat_kernel<<<sgrid, 64>>>(raypos, raydir, tminmax, primpos, primrot, primscale);
    composite_kernel<<<HW/256, 256>>>(tminmax, out, out_size);
}

// round 6
// speedup vs baseline: 34.1508x; 1.3421x over previous
#include <cuda_runtime.h>
#include <cstdint>

#define Wd 256
#define Hd 256
#define HW (Wd*Hd)
#define KP 64
#define NSTEP 64
#define DT (1.0f/256.0f)
#define INV_DT 256.0f
#define VOLR 256.0f

#define STEP_CHUNKS 4
#define CHUNK (NSTEP/STEP_CHUNKS)
#define MAX_SUBT 64

// Transposed voxel template: [k][z][y][x] -> float4(c0..c3). 4 MB.
__device__ float4 g_vox[KP * 4096];
// Per-(step, ray) accumulated sample: [step][ray]. 64 MB (only bbox region used).
__device__ float4 g_s[NSTEP * HW];
// Union screen bbox of all prims: wlo, whi, hlo, hhi
__device__ int g_bb[4];

// ---------------------------------------------------------------- bbox ----
__global__ void bbox_kernel(const float* __restrict__ primpos,
                            const float* __restrict__ primrot,
                            const float* __restrict__ primscale)
{
    __shared__ int s4[4][2];   // [coord][warp]
    const int k = threadIdx.x; // 64 threads, one per prim
    const float px = primpos[k*3+0] * (1.0f/VOLR);
    const float py = primpos[k*3+1] * (1.0f/VOLR);
    float rot[9];
    #pragma unroll
    for (int i = 0; i < 9; i++) rot[i] = primrot[k*9+i];
    const float isx = 1.0f/primscale[k*3+0];
    const float isy = 1.0f/primscale[k*3+1];
    const float isz = 1.0f/primscale[k*3+2];
    const float ex = fabsf(rot[0])*isx + fabsf(rot[1])*isy + fabsf(rot[2])*isz;
    const float ey = fabsf(rot[3])*isx + fabsf(rot[4])*isy + fabsf(rot[5])*isz;

    int wlo = (int)floorf((px - ex + 1.0f) * 127.5f) - 1;
    int whi = (int)ceilf ((px + ex + 1.0f) * 127.5f) + 1;
    int hlo = (int)floorf((py - ey + 1.0f) * 127.5f) - 1;
    int hhi = (int)ceilf ((py + ey + 1.0f) * 127.5f) + 1;

    #pragma unroll
    for (int off = 16; off; off >>= 1) {
        wlo = min(wlo, __shfl_xor_sync(0xFFFFFFFFu, wlo, off));
        hlo = min(hlo, __shfl_xor_sync(0xFFFFFFFFu, hlo, off));
        whi = max(whi, __shfl_xor_sync(0xFFFFFFFFu, whi, off));
        hhi = max(hhi, __shfl_xor_sync(0xFFFFFFFFu, hhi, off));
    }
    const int warp = threadIdx.x >> 5;
    if ((threadIdx.x & 31) == 0) {
        s4[0][warp] = wlo; s4[1][warp] = whi;
        s4[2][warp] = hlo; s4[3][warp] = hhi;
    }
    __syncthreads();
    if (threadIdx.x == 0) {
        g_bb[0] = max(min(s4[0][0], s4[0][1]), 0);
        g_bb[1] = min(max(s4[1][0], s4[1][1]), Wd-1);
        g_bb[2] = max(min(s4[2][0], s4[2][1]), 0);
        g_bb[3] = min(max(s4[3][0], s4[3][1]), Hd-1);
    }
}

// ---------------------------------------------------------------- zero ----
__global__ void zero_s_kernel() {
    int i = blockIdx.x * blockDim.x + threadIdx.x;   // NSTEP*HW threads
    int r = i & (HW - 1);
    int w = r & (Wd - 1), h = r >> 8;
    if (w < g_bb[0] || w > g_bb[1] || h < g_bb[2] || h > g_bb[3]) return;
    g_s[i] = make_float4(0.f, 0.f, 0.f, 0.f);
}

// ----------------------------------------------------------- transpose ----
__global__ void transpose_vox_kernel(const float* __restrict__ rgba) {
    int v = blockIdx.x * blockDim.x + threadIdx.x;   // 0 .. KP*4096-1
    if (v >= KP * 4096) return;
    int k = v >> 12;
    int off = v & 4095;
    const float* b = rgba + (size_t)k * 16384 + off; // [k][c][4096]
    g_vox[v] = make_float4(b[0], b[4096], b[8192], b[12288]);
}

// --------------------------------------------------------------- splat ----
// One block = one 8x8 ray subtile of one prim's bbox, one 16-step chunk.
// grid = (MAX_SUBT, KP, STEP_CHUNKS)
__global__ void __launch_bounds__(64)
splat_kernel(const float* __restrict__ raypos, const float* __restrict__ raydir,
             const float* __restrict__ tminmax, const float* __restrict__ primpos,
             const float* __restrict__ primrot, const float* __restrict__ primscale)
{
    const int k = blockIdx.y;

    const float px = primpos[k*3+0] * (1.0f/VOLR);
    const float py = primpos[k*3+1] * (1.0f/VOLR);
    const float pz = primpos[k*3+2] * (1.0f/VOLR);
    const float sx = primscale[k*3+0];
    const float sy = primscale[k*3+1];
    const float sz = primscale[k*3+2];
    float rot[9];
    #pragma unroll
    for (int i = 0; i < 9; i++) rot[i] = primrot[k*9+i];

    const float isx = 1.0f/sx, isy = 1.0f/sy, isz = 1.0f/sz;
    const float ex = fabsf(rot[0])*isx + fabsf(rot[1])*isy + fabsf(rot[2])*isz;
    const float ey = fabsf(rot[3])*isx + fabsf(rot[4])*isy + fabsf(rot[5])*isz;

    int wlo = (int)floorf((px - ex + 1.0f) * 127.5f) - 1;
    int whi = (int)ceilf ((px + ex + 1.0f) * 127.5f) + 1;
    int hlo = (int)floorf((py - ey + 1.0f) * 127.5f) - 1;
    int hhi = (int)ceilf ((py + ey + 1.0f) * 127.5f) + 1;
    wlo = max(wlo, 0); whi = min(whi, Wd-1);
    hlo = max(hlo, 0); hhi = min(hhi, Hd-1);
    if (whi < wlo || hhi < hlo) return;

    const int bw = ((whi - wlo) >> 3) + 1;
    const int bh = ((hhi - hlo) >> 3) + 1;
    const int bidx = blockIdx.x;
    if (bidx >= bw * bh) return;

    const int w = wlo + (bidx % bw) * 8 + (threadIdx.x & 7);
    const int h = hlo + (bidx / bw) * 8 + (threadIdx.x >> 3);
    if (w > whi || h > hhi) return;
    const int r = h * Wd + w;

    const float ox = raypos[r*3+0], oy = raypos[r*3+1], oz = raypos[r*3+2];
    const float dx = raydir[r*3+0], dy = raydir[r*3+1], dz = raydir[r*3+2];
    const float tmn = tminmax[r*2+0], tmx = tminmax[r*2+1];

    // local(t) = a + t*b
    const float rx = ox - px, ry = oy - py, rz = oz - pz;
    const float ax = (rot[0]*rx + rot[3]*ry + rot[6]*rz) * sx;
    const float ay = (rot[1]*rx + rot[4]*ry + rot[7]*rz) * sy;
    const float az = (rot[2]*rx + rot[5]*ry + rot[8]*rz) * sz;
    const float bx = (rot[0]*dx + rot[3]*dy + rot[6]*dz) * sx;
    const float by = (rot[1]*dx + rot[4]*dy + rot[7]*dz) * sy;
    const float bz = (rot[2]*dx + rot[5]*dy + rot[8]*dz) * sz;

    float t0 = tmn, t1 = tmx;
    #pragma unroll
    for (int ax3 = 0; ax3 < 3; ax3++) {
        float a = (ax3 == 0) ? ax : (ax3 == 1) ? ay : az;
        float b = (ax3 == 0) ? bx : (ax3 == 1) ? by : bz;
        if (fabsf(b) > 1e-9f) {
            float inv = 1.0f / b;
            float l = (-1.0f - a) * inv;
            float hgh = (1.0f - a) * inv;
            t0 = fmaxf(t0, fminf(l, hgh));
            t1 = fminf(t1, fmaxf(l, hgh));
        } else if (fabsf(a) >= 1.0f) {
            t1 = -1e30f;
        }
    }
    int ilo = (int)ceilf((t0 - tmn) * INV_DT - 0.51f);
    int ihi = (int)floorf((t1 - tmn) * INV_DT - 0.49f);
    // clip to this block's step chunk
    ilo = max(ilo, (int)blockIdx.z * CHUNK);
    ihi = min(ihi, (int)blockIdx.z * CHUNK + CHUNK - 1);
    ihi = min(ihi, NSTEP - 1);
    if (ihi < ilo) return;

    const float4* vk = g_vox + k * 4096;

    for (int i = ilo; i <= ihi; i++) {
        float t = tmn + ((float)i + 0.5f) * DT;
        float lx = fmaf(t, bx, ax);
        float ly = fmaf(t, by, ay);
        float lz = fmaf(t, bz, az);
        if (!(fabsf(lx) < 1.0f && fabsf(ly) < 1.0f && fabsf(lz) < 1.0f)) continue;

        float gx = fminf(fmaxf((lx + 1.0f) * 7.5f, 0.0f), 15.0f - 1e-5f);
        float gy = fminf(fmaxf((ly + 1.0f) * 7.5f, 0.0f), 15.0f - 1e-5f);
        float gz = fminf(fmaxf((lz + 1.0f) * 7.5f, 0.0f), 15.0f - 1e-5f);
        int x0 = min((int)gx, 14);
        int y0 = min((int)gy, 14);
        int z0 = min((int)gz, 14);
        float fx = gx - (float)x0, fy = gy - (float)y0, fz = gz - (float)z0;

        const float4* base = vk + ((z0*16 + y0)*16 + x0);
        float4 v000 = base[0],   v001 = base[1];
        float4 v010 = base[16],  v011 = base[17];
        float4 v100 = base[256], v101 = base[257];
        float4 v110 = base[272], v111 = base[273];

        float w0z = 1.f - fz, w0y = 1.f - fy, w0x = 1.f - fx;
        float w00 = w0z*w0y, w01 = w0z*fy, w10 = fz*w0y, w11 = fz*fy;
        float w000 = w00*w0x, w001 = w00*fx;
        float w010 = w01*w0x, w011 = w01*fx;
        float w100 = w10*w0x, w101 = w10*fx;
        float w110 = w11*w0x, w111 = w11*fx;

        float s0 = fmaf(v000.x,w000,fmaf(v001.x,w001,fmaf(v010.x,w010,fmaf(v011.x,w011,
                   fmaf(v100.x,w100,fmaf(v101.x,w101,fmaf(v110.x,w110,v111.x*w111)))))));
        float s1 = fmaf(v000.y,w000,fmaf(v001.y,w001,fmaf(v010.y,w010,fmaf(v011.y,w011,
                   fmaf(v100.y,w100,fmaf(v101.y,w101,fmaf(v110.y,w110,v111.y*w111)))))));
        float s2 = fmaf(v000.z,w000,fmaf(v001.z,w001,fmaf(v010.z,w010,fmaf(v011.z,w011,
                   fmaf(v100.z,w100,fmaf(v101.z,w101,fmaf(v110.z,w110,v111.z*w111)))))));
        float s3 = fmaf(v000.w,w000,fmaf(v001.w,w001,fmaf(v010.w,w010,fmaf(v011.w,w011,
                   fmaf(v100.w,w100,fmaf(v101.w,w101,fmaf(v110.w,w110,v111.w*w111)))))));

        float* dst = (float*)&g_s[i * HW + r];
        asm volatile("red.global.add.v4.f32 [%0], {%1, %2, %3, %4};"
                     :: "l"(dst), "f"(s0), "f"(s1), "f"(s2), "f"(s3) : "memory");
    }
}

// ----------------------------------------------------------- composite ----
__global__ void __launch_bounds__(256)
composite_kernel(const float* __restrict__ tminmax, float* __restrict__ out, int out_size)
{
    const int r = blockIdx.x * 256 + threadIdx.x;
    const int w = r & (Wd - 1), h = r >> 8;

    float crx = 0.f, cry = 0.f, crz = 0.f, alpha = 0.f;
    if (!(w < g_bb[0] || w > g_bb[1] || h < g_bb[2] || h > g_bb[3])) {
        const float tmn = tminmax[r*2+0], tmx = tminmax[r*2+1];
        #pragma unroll 8
        for (int i = 0; i < NSTEP; i++) {
            float4 s = g_s[i * HW + r];
            float t = tmn + ((float)i + 0.5f) * DT;
            float contrib = fminf(1.0f, fmaf(s.w, DT, alpha)) - alpha;
            if (!(t < tmx)) contrib = 0.0f;
            crx = fmaf(s.x, contrib, crx);
            cry = fmaf(s.y, contrib, cry);
            crz = fmaf(s.z, contrib, crz);
            alpha += contrib;
        }
    }

    if (out_size >= 8 * HW) {
        out[0*HW + r] = crx; out[1*HW + r] = cry; out[2*HW + r] = crz;
        out[3*HW + r] = alpha;
        out[4*HW + r] = crx; out[5*HW + r] = cry; out[6*HW + r] = crz;
        out[7*HW + r] = alpha;
    } else {
        out[0*HW + r] = crx; out[1*HW + r] = cry; out[2*HW + r] = crz;
        out[3*HW + r] = alpha;
    }
}

extern "C" void kernel_launch(void* const* d_in, const int* in_sizes, int n_in,
                              void* d_out, int out_size) {
    const float* raypos    = (const float*)d_in[0];
    const float* raydir    = (const float*)d_in[1];
    const float* tminmax   = (const float*)d_in[2];
    const float* primpos   = (const float*)d_in[3];
    const float* primrot   = (const float*)d_in[4];
    const float* primscale = (const float*)d_in[5];
    const float* primrgba  = (const float*)d_in[6];
    float* out = (float*)d_out;

    bbox_kernel<<<1, 64>>>(primpos, primrot, primscale);
    transpose_vox_kernel<<<(KP*4096 + 255)/256, 256>>>(primrgba);
    zero_s_kernel<<<(NSTEP*HW)/256, 256>>>();
    dim3 sgrid(MAX_SUBT, KP, STEP_CHUNKS);
    splat_kernel<<<sgrid, 64>>>(raypos, raydir, tminmax, primpos, primrot, primscale);
    composite_kernel<<<HW/256, 256>>>(tminmax, out, out_size);
}

// round 7
// speedup vs baseline: 40.3789x; 1.1824x over previous
#include <cuda_runtime.h>
#include <cstdint>

#define Wd 256
#define Hd 256
#define HW (Wd*Hd)
#define KP 64
#define NSTEP 64
#define DT (1.0f/256.0f)
#define INV_DT 256.0f
#define VOLR 256.0f

#define STEP_CHUNKS 8
#define CHUNK (NSTEP/STEP_CHUNKS)
#define MAX_SUBT 64

// Transposed voxel template: [k][z][y][x] -> float4(c0..c3). 4 MB.
__device__ float4 g_vox[KP * 4096];
// Per-(step, ray) accumulated sample: [step][ray]. 64 MB (only bbox region used).
__device__ float4 g_s[NSTEP * HW];
// Per-prim derived data: [0..2]=pos, [3..11]=rot*scale (mx0..mz2)
__device__ float g_ppf[KP][12];
// Per-prim ints: wlo, whi, hlo, hhi, bw, bh
__device__ int g_ppi[KP][6];

// Inline union-bbox over all prims, computed redundantly per block.
// Requires blockDim.x >= 64. sbb[0..3] = wlo, whi, hlo, hhi on return.
__device__ __forceinline__ void block_bbox(const float* __restrict__ primpos,
                                           const float* __restrict__ primrot,
                                           const float* __restrict__ primscale,
                                           int* sbb, int tid)
{
    __shared__ int tmp[4][2];
    if (tid < 64) {
        const int k = tid;
        const float px = primpos[k*3+0] * (1.0f/VOLR);
        const float py = primpos[k*3+1] * (1.0f/VOLR);
        float r0 = primrot[k*9+0], r1 = primrot[k*9+1], r2 = primrot[k*9+2];
        float r3 = primrot[k*9+3], r4 = primrot[k*9+4], r5 = primrot[k*9+5];
        const float isx = 1.0f/primscale[k*3+0];
        const float isy = 1.0f/primscale[k*3+1];
        const float isz = 1.0f/primscale[k*3+2];
        const float ex = fabsf(r0)*isx + fabsf(r1)*isy + fabsf(r2)*isz;
        const float ey = fabsf(r3)*isx + fabsf(r4)*isy + fabsf(r5)*isz;
        int wlo = (int)floorf((px - ex + 1.0f) * 127.5f) - 1;
        int whi = (int)ceilf ((px + ex + 1.0f) * 127.5f) + 1;
        int hlo = (int)floorf((py - ey + 1.0f) * 127.5f) - 1;
        int hhi = (int)ceilf ((py + ey + 1.0f) * 127.5f) + 1;
        #pragma unroll
        for (int off = 16; off; off >>= 1) {
            wlo = min(wlo, __shfl_xor_sync(0xFFFFFFFFu, wlo, off));
            hlo = min(hlo, __shfl_xor_sync(0xFFFFFFFFu, hlo, off));
            whi = max(whi, __shfl_xor_sync(0xFFFFFFFFu, whi, off));
            hhi = max(hhi, __shfl_xor_sync(0xFFFFFFFFu, hhi, off));
        }
        const int warp = tid >> 5;
        if ((tid & 31) == 0) {
            tmp[0][warp] = wlo; tmp[1][warp] = whi;
            tmp[2][warp] = hlo; tmp[3][warp] = hhi;
        }
    }
    __syncthreads();
    if (tid == 0) {
        sbb[0] = max(min(tmp[0][0], tmp[0][1]), 0);
        sbb[1] = min(max(tmp[1][0], tmp[1][1]), Wd-1);
        sbb[2] = max(min(tmp[2][0], tmp[2][1]), 0);
        sbb[3] = min(max(tmp[3][0], tmp[3][1]), Hd-1);
    }
    __syncthreads();
}

// ---------------------------------------------------------------- prep ----
// blocks [0,1024): voxel transpose
// block 1024: per-prim derived data
// blocks (1024, 5120]: zero g_s (gated by inline bbox)
#define TR_BLOCKS 1024
#define ZERO_BLOCKS 4096
__global__ void __launch_bounds__(256)
prep_kernel(const float* __restrict__ rgba, const float* __restrict__ primpos,
            const float* __restrict__ primrot, const float* __restrict__ primscale)
{
    const int tid = threadIdx.x;
    const int b = blockIdx.x;

    if (b < TR_BLOCKS) {
        int v = b * 256 + tid;                 // 0 .. KP*4096-1
        int k = v >> 12;
        int off = v & 4095;
        const float* src = rgba + (size_t)k * 16384 + off; // [k][c][4096]
        g_vox[v] = make_float4(src[0], src[4096], src[8192], src[12288]);
        return;
    }

    if (b == TR_BLOCKS) {
        if (tid < KP) {
            const int k = tid;
            const float px = primpos[k*3+0] * (1.0f/VOLR);
            const float py = primpos[k*3+1] * (1.0f/VOLR);
            const float pz = primpos[k*3+2] * (1.0f/VOLR);
            const float sx = primscale[k*3+0];
            const float sy = primscale[k*3+1];
            const float sz = primscale[k*3+2];
            float rot[9];
            #pragma unroll
            for (int i = 0; i < 9; i++) rot[i] = primrot[k*9+i];

            g_ppf[k][0] = px; g_ppf[k][1] = py; g_ppf[k][2] = pz;
            // local_x uses rot column 0 (rot[0],rot[3],rot[6]) * sx, etc.
            g_ppf[k][3]  = rot[0]*sx; g_ppf[k][4]  = rot[3]*sx; g_ppf[k][5]  = rot[6]*sx;
            g_ppf[k][6]  = rot[1]*sy; g_ppf[k][7]  = rot[4]*sy; g_ppf[k][8]  = rot[7]*sy;
            g_ppf[k][9]  = rot[2]*sz; g_ppf[k][10] = rot[5]*sz; g_ppf[k][11] = rot[8]*sz;

            const float isx = 1.0f/sx, isy = 1.0f/sy, isz = 1.0f/sz;
            const float ex = fabsf(rot[0])*isx + fabsf(rot[1])*isy + fabsf(rot[2])*isz;
            const float ey = fabsf(rot[3])*isx + fabsf(rot[4])*isy + fabsf(rot[5])*isz;
            int wlo = max((int)floorf((px - ex + 1.0f) * 127.5f) - 1, 0);
            int whi = min((int)ceilf ((px + ex + 1.0f) * 127.5f) + 1, Wd-1);
            int hlo = max((int)floorf((py - ey + 1.0f) * 127.5f) - 1, 0);
            int hhi = min((int)ceilf ((py + ey + 1.0f) * 127.5f) + 1, Hd-1);
            g_ppi[k][0] = wlo; g_ppi[k][1] = whi;
            g_ppi[k][2] = hlo; g_ppi[k][3] = hhi;
            g_ppi[k][4] = (whi >= wlo) ? ((whi - wlo) >> 3) + 1 : 0;
            g_ppi[k][5] = (hhi >= hlo) ? ((hhi - hlo) >> 3) + 1 : 0;
        }
        return;
    }

    // zero role
    __shared__ int sbb[4];
    block_bbox(primpos, primrot, primscale, sbb, tid);
    const int zb = b - (TR_BLOCKS + 1);
    #pragma unroll
    for (int j = 0; j < 4; j++) {
        int i = zb * 1024 + j * 256 + tid;     // < NSTEP*HW
        int r = i & (HW - 1);
        int w = r & (Wd - 1), h = (r >> 8) & (Hd - 1);
        if (w < sbb[0] || w > sbb[1] || h < sbb[2] || h > sbb[3]) continue;
        g_s[i] = make_float4(0.f, 0.f, 0.f, 0.f);
    }
}

// --------------------------------------------------------------- splat ----
// One block = one 8x8 ray subtile of one prim's bbox, one 8-step chunk.
// grid = (MAX_SUBT, KP, STEP_CHUNKS)
__global__ void __launch_bounds__(64)
splat_kernel(const float* __restrict__ raypos, const float* __restrict__ raydir,
             const float* __restrict__ tminmax)
{
    const int k = blockIdx.y;
    const int* I = g_ppi[k];
    const int bw = I[4];
    const int bidx = blockIdx.x;
    if (bidx >= bw * I[5]) return;

    const int w = I[0] + (bidx % bw) * 8 + (threadIdx.x & 7);
    const int h = I[2] + (bidx / bw) * 8 + (threadIdx.x >> 3);
    if (w > I[1] || h > I[3]) return;
    const int r = h * Wd + w;

    const float* F = g_ppf[k];
    const float px = F[0], py = F[1], pz = F[2];

    const float ox = raypos[r*3+0], oy = raypos[r*3+1], oz = raypos[r*3+2];
    const float dx = raydir[r*3+0], dy = raydir[r*3+1], dz = raydir[r*3+2];
    const float tmn = tminmax[r*2+0], tmx = tminmax[r*2+1];

    // local(t) = a + t*b
    const float rx = ox - px, ry = oy - py, rz = oz - pz;
    const float ax = F[3]*rx + F[4]*ry + F[5]*rz;
    const float ay = F[6]*rx + F[7]*ry + F[8]*rz;
    const float az = F[9]*rx + F[10]*ry + F[11]*rz;
    const float bx = F[3]*dx + F[4]*dy + F[5]*dz;
    const float by = F[6]*dx + F[7]*dy + F[8]*dz;
    const float bz = F[9]*dx + F[10]*dy + F[11]*dz;

    float t0 = tmn, t1 = tmx;
    #pragma unroll
    for (int ax3 = 0; ax3 < 3; ax3++) {
        float a = (ax3 == 0) ? ax : (ax3 == 1) ? ay : az;
        float b = (ax3 == 0) ? bx : (ax3 == 1) ? by : bz;
        if (fabsf(b) > 1e-9f) {
            float inv = 1.0f / b;
            float l = (-1.0f - a) * inv;
            float hgh = (1.0f - a) * inv;
            t0 = fmaxf(t0, fminf(l, hgh));
            t1 = fminf(t1, fmaxf(l, hgh));
        } else if (fabsf(a) >= 1.0f) {
            t1 = -1e30f;
        }
    }
    int ilo = (int)ceilf((t0 - tmn) * INV_DT - 0.51f);
    int ihi = (int)floorf((t1 - tmn) * INV_DT - 0.49f);
    ilo = max(ilo, (int)blockIdx.z * CHUNK);
    ihi = min(ihi, (int)blockIdx.z * CHUNK + CHUNK - 1);
    ihi = min(ihi, NSTEP - 1);
    if (ihi < ilo) return;

    const float4* vk = g_vox + k * 4096;

    for (int i = ilo; i <= ihi; i++) {
        float t = tmn + ((float)i + 0.5f) * DT;
        float lx = fmaf(t, bx, ax);
        float ly = fmaf(t, by, ay);
        float lz = fmaf(t, bz, az);
        if (!(fabsf(lx) < 1.0f && fabsf(ly) < 1.0f && fabsf(lz) < 1.0f)) continue;

        float gx = fminf(fmaxf((lx + 1.0f) * 7.5f, 0.0f), 15.0f - 1e-5f);
        float gy = fminf(fmaxf((ly + 1.0f) * 7.5f, 0.0f), 15.0f - 1e-5f);
        float gz = fminf(fmaxf((lz + 1.0f) * 7.5f, 0.0f), 15.0f - 1e-5f);
        int x0 = min((int)gx, 14);
        int y0 = min((int)gy, 14);
        int z0 = min((int)gz, 14);
        float fx = gx - (float)x0, fy = gy - (float)y0, fz = gz - (float)z0;

        const float4* base = vk + ((z0*16 + y0)*16 + x0);
        float4 v000 = base[0],   v001 = base[1];
        float4 v010 = base[16],  v011 = base[17];
        float4 v100 = base[256], v101 = base[257];
        float4 v110 = base[272], v111 = base[273];

        float w0z = 1.f - fz, w0y = 1.f - fy, w0x = 1.f - fx;
        float w00 = w0z*w0y, w01 = w0z*fy, w10 = fz*w0y, w11 = fz*fy;
        float w000 = w00*w0x, w001 = w00*fx;
        float w010 = w01*w0x, w011 = w01*fx;
        float w100 = w10*w0x, w101 = w10*fx;
        float w110 = w11*w0x, w111 = w11*fx;

        float s0 = fmaf(v000.x,w000,fmaf(v001.x,w001,fmaf(v010.x,w010,fmaf(v011.x,w011,
                   fmaf(v100.x,w100,fmaf(v101.x,w101,fmaf(v110.x,w110,v111.x*w111)))))));
        float s1 = fmaf(v000.y,w000,fmaf(v001.y,w001,fmaf(v010.y,w010,fmaf(v011.y,w011,
                   fmaf(v100.y,w100,fmaf(v101.y,w101,fmaf(v110.y,w110,v111.y*w111)))))));
        float s2 = fmaf(v000.z,w000,fmaf(v001.z,w001,fmaf(v010.z,w010,fmaf(v011.z,w011,
                   fmaf(v100.z,w100,fmaf(v101.z,w101,fmaf(v110.z,w110,v111.z*w111)))))));
        float s3 = fmaf(v000.w,w000,fmaf(v001.w,w001,fmaf(v010.w,w010,fmaf(v011.w,w011,
                   fmaf(v100.w,w100,fmaf(v101.w,w101,fmaf(v110.w,w110,v111.w*w111)))))));

        float* dst = (float*)&g_s[i * HW + r];
        asm volatile("red.global.add.v4.f32 [%0], {%1, %2, %3, %4};"
                     :: "l"(dst), "f"(s0), "f"(s1), "f"(s2), "f"(s3) : "memory");
    }
}

// ----------------------------------------------------------- composite ----
__global__ void __launch_bounds__(256)
composite_kernel(const float* __restrict__ tminmax,
                 const float* __restrict__ primpos, const float* __restrict__ primrot,
                 const float* __restrict__ primscale,
                 float* __restrict__ out, int out_size)
{
    __shared__ int sbb[4];
    const int tid = threadIdx.x;
    block_bbox(primpos, primrot, primscale, sbb, tid);

    const int r = blockIdx.x * 256 + tid;
    const int w = r & (Wd - 1), h = r >> 8;

    float crx = 0.f, cry = 0.f, crz = 0.f, alpha = 0.f;
    if (!(w < sbb[0] || w > sbb[1] || h < sbb[2] || h > sbb[3])) {
        const float tmn = tminmax[r*2+0], tmx = tminmax[r*2+1];
        #pragma unroll 8
        for (int i = 0; i < NSTEP; i++) {
            float4 s = g_s[i * HW + r];
            float t = tmn + ((float)i + 0.5f) * DT;
            float contrib = fminf(1.0f, fmaf(s.w, DT, alpha)) - alpha;
            if (!(t < tmx)) contrib = 0.0f;
            crx = fmaf(s.x, contrib, crx);
            cry = fmaf(s.y, contrib, cry);
            crz = fmaf(s.z, contrib, crz);
            alpha += contrib;
        }
    }

    if (out_size >= 8 * HW) {
        out[0*HW + r] = crx; out[1*HW + r] = cry; out[2*HW + r] = crz;
        out[3*HW + r] = alpha;
        out[4*HW + r] = crx; out[5*HW + r] = cry; out[6*HW + r] = crz;
        out[7*HW + r] = alpha;
    } else {
        out[0*HW + r] = crx; out[1*HW + r] = cry; out[2*HW + r] = crz;
        out[3*HW + r] = alpha;
    }
}

extern "C" void kernel_launch(void* const* d_in, const int* in_sizes, int n_in,
                              void* d_out, int out_size) {
    const float* raypos    = (const float*)d_in[0];
    const float* raydir    = (const float*)d_in[1];
    const float* tminmax   = (const float*)d_in[2];
    const float* primpos   = (const float*)d_in[3];
    const float* primrot   = (const float*)d_in[4];
    const float* primscale = (const float*)d_in[5];
    const float* primrgba  = (const float*)d_in[6];
    float* out = (float*)d_out;

    prep_kernel<<<TR_BLOCKS + 1 + ZERO_BLOCKS, 256>>>(primrgba, primpos, primrot, primscale);
    dim3 sgrid(MAX_SUBT, KP, STEP_CHUNKS);
    splat_kernel<<<sgrid, 64>>>(raypos, raydir, tminmax);
    composite_kernel<<<HW/256, 256>>>(tminmax, primpos, primrot, primscale, out, out_size);
}

// round 8
// speedup vs baseline: 42.6158x; 1.0554x over previous
#include <cuda_runtime.h>
#include <cuda_fp16.h>
#include <cstdint>

#define Wd 256
#define Hd 256
#define HW (Wd*Hd)
#define KP 64
#define NSTEP 64
#define DT (1.0f/256.0f)
#define INV_DT 256.0f
#define VOLR 256.0f

#define STEP_CHUNKS 8
#define CHUNK (NSTEP/STEP_CHUNKS)
#define MAX_SUBT 64

// Voxel template in fp16: [k][z][y][x] -> 4 halves (c0..c3) packed in uint2. 2 MB.
__device__ uint2 g_vox[KP * 4096];
// Per-(step, ray) accumulated sample: [step][ray]. 64 MB (only bbox region used).
__device__ float4 g_s[NSTEP * HW];
// Per-prim derived data: [0..2]=pos, [3..11]=rot*scale
__device__ float g_ppf[KP][12];
// Per-prim ints: wlo, whi, hlo, hhi, bw, bh
__device__ int g_ppi[KP][6];

// Inline union-bbox over all prims, computed redundantly per block.
__device__ __forceinline__ void block_bbox(const float* __restrict__ primpos,
                                           const float* __restrict__ primrot,
                                           const float* __restrict__ primscale,
                                           int* sbb, int tid)
{
    __shared__ int tmp[4][2];
    if (tid < 64) {
        const int k = tid;
        const float px = primpos[k*3+0] * (1.0f/VOLR);
        const float py = primpos[k*3+1] * (1.0f/VOLR);
        float r0 = primrot[k*9+0], r1 = primrot[k*9+1], r2 = primrot[k*9+2];
        float r3 = primrot[k*9+3], r4 = primrot[k*9+4], r5 = primrot[k*9+5];
        const float isx = 1.0f/primscale[k*3+0];
        const float isy = 1.0f/primscale[k*3+1];
        const float isz = 1.0f/primscale[k*3+2];
        const float ex = fabsf(r0)*isx + fabsf(r1)*isy + fabsf(r2)*isz;
        const float ey = fabsf(r3)*isx + fabsf(r4)*isy + fabsf(r5)*isz;
        int wlo = (int)floorf((px - ex + 1.0f) * 127.5f) - 1;
        int whi = (int)ceilf ((px + ex + 1.0f) * 127.5f) + 1;
        int hlo = (int)floorf((py - ey + 1.0f) * 127.5f) - 1;
        int hhi = (int)ceilf ((py + ey + 1.0f) * 127.5f) + 1;
        #pragma unroll
        for (int off = 16; off; off >>= 1) {
            wlo = min(wlo, __shfl_xor_sync(0xFFFFFFFFu, wlo, off));
            hlo = min(hlo, __shfl_xor_sync(0xFFFFFFFFu, hlo, off));
            whi = max(whi, __shfl_xor_sync(0xFFFFFFFFu, whi, off));
            hhi = max(hhi, __shfl_xor_sync(0xFFFFFFFFu, hhi, off));
        }
        const int warp = tid >> 5;
        if ((tid & 31) == 0) {
            tmp[0][warp] = wlo; tmp[1][warp] = whi;
            tmp[2][warp] = hlo; tmp[3][warp] = hhi;
        }
    }
    __syncthreads();
    if (tid == 0) {
        sbb[0] = max(min(tmp[0][0], tmp[0][1]), 0);
        sbb[1] = min(max(tmp[1][0], tmp[1][1]), Wd-1);
        sbb[2] = max(min(tmp[2][0], tmp[2][1]), 0);
        sbb[3] = min(max(tmp[3][0], tmp[3][1]), Hd-1);
    }
    __syncthreads();
}

// ---------------------------------------------------------------- prep ----
#define TR_BLOCKS 1024
#define ZERO_BLOCKS 4096
__global__ void __launch_bounds__(256)
prep_kernel(const float* __restrict__ rgba, const float* __restrict__ primpos,
            const float* __restrict__ primrot, const float* __restrict__ primscale)
{
    const int tid = threadIdx.x;
    const int b = blockIdx.x;

    if (b < TR_BLOCKS) {
        int v = b * 256 + tid;                 // 0 .. KP*4096-1
        int k = v >> 12;
        int off = v & 4095;
        const float* src = rgba + (size_t)k * 16384 + off; // [k][c][4096]
        __half2 h01 = __floats2half2_rn(src[0],    src[4096]);
        __half2 h23 = __floats2half2_rn(src[8192], src[12288]);
        uint2 u;
        u.x = *reinterpret_cast<unsigned*>(&h01);
        u.y = *reinterpret_cast<unsigned*>(&h23);
        g_vox[v] = u;
        return;
    }

    if (b == TR_BLOCKS) {
        if (tid < KP) {
            const int k = tid;
            const float px = primpos[k*3+0] * (1.0f/VOLR);
            const float py = primpos[k*3+1] * (1.0f/VOLR);
            const float pz = primpos[k*3+2] * (1.0f/VOLR);
            const float sx = primscale[k*3+0];
            const float sy = primscale[k*3+1];
            const float sz = primscale[k*3+2];
            float rot[9];
            #pragma unroll
            for (int i = 0; i < 9; i++) rot[i] = primrot[k*9+i];

            g_ppf[k][0] = px; g_ppf[k][1] = py; g_ppf[k][2] = pz;
            g_ppf[k][3]  = rot[0]*sx; g_ppf[k][4]  = rot[3]*sx; g_ppf[k][5]  = rot[6]*sx;
            g_ppf[k][6]  = rot[1]*sy; g_ppf[k][7]  = rot[4]*sy; g_ppf[k][8]  = rot[7]*sy;
            g_ppf[k][9]  = rot[2]*sz; g_ppf[k][10] = rot[5]*sz; g_ppf[k][11] = rot[8]*sz;

            const float isx = 1.0f/sx, isy = 1.0f/sy, isz = 1.0f/sz;
            const float ex = fabsf(rot[0])*isx + fabsf(rot[1])*isy + fabsf(rot[2])*isz;
            const float ey = fabsf(rot[3])*isx + fabsf(rot[4])*isy + fabsf(rot[5])*isz;
            int wlo = max((int)floorf((px - ex + 1.0f) * 127.5f) - 1, 0);
            int whi = min((int)ceilf ((px + ex + 1.0f) * 127.5f) + 1, Wd-1);
            int hlo = max((int)floorf((py - ey + 1.0f) * 127.5f) - 1, 0);
            int hhi = min((int)ceilf ((py + ey + 1.0f) * 127.5f) + 1, Hd-1);
            g_ppi[k][0] = wlo; g_ppi[k][1] = whi;
            g_ppi[k][2] = hlo; g_ppi[k][3] = hhi;
            g_ppi[k][4] = (whi >= wlo) ? ((whi - wlo) >> 3) + 1 : 0;
            g_ppi[k][5] = (hhi >= hlo) ? ((hhi - hlo) >> 3) + 1 : 0;
        }
        return;
    }

    // zero role
    __shared__ int sbb[4];
    block_bbox(primpos, primrot, primscale, sbb, tid);
    const int zb = b - (TR_BLOCKS + 1);
    #pragma unroll
    for (int j = 0; j < 4; j++) {
        int i = zb * 1024 + j * 256 + tid;     // < NSTEP*HW
        int r = i & (HW - 1);
        int w = r & (Wd - 1), h = (r >> 8) & (Hd - 1);
        if (w < sbb[0] || w > sbb[1] || h < sbb[2] || h > sbb[3]) continue;
        g_s[i] = make_float4(0.f, 0.f, 0.f, 0.f);
    }
}

// --------------------------------------------------------------- splat ----
// One block = one 8x8 ray subtile of one prim's bbox, one 8-step chunk.
__global__ void __launch_bounds__(64)
splat_kernel(const float* __restrict__ raypos, const float* __restrict__ raydir,
             const float* __restrict__ tminmax)
{
    const int k = blockIdx.y;
    const int* I = g_ppi[k];
    const int bw = I[4];
    const int bidx = blockIdx.x;
    if (bidx >= bw * I[5]) return;

    const int w = I[0] + (bidx % bw) * 8 + (threadIdx.x & 7);
    const int h = I[2] + (bidx / bw) * 8 + (threadIdx.x >> 3);
    if (w > I[1] || h > I[3]) return;
    const int r = h * Wd + w;

    const float* F = g_ppf[k];
    const float px = F[0], py = F[1], pz = F[2];

    const float ox = raypos[r*3+0], oy = raypos[r*3+1], oz = raypos[r*3+2];
    const float dx = raydir[r*3+0], dy = raydir[r*3+1], dz = raydir[r*3+2];
    const float tmn = tminmax[r*2+0], tmx = tminmax[r*2+1];

    const float rx = ox - px, ry = oy - py, rz = oz - pz;
    const float ax = F[3]*rx + F[4]*ry + F[5]*rz;
    const float ay = F[6]*rx + F[7]*ry + F[8]*rz;
    const float az = F[9]*rx + F[10]*ry + F[11]*rz;
    const float bx = F[3]*dx + F[4]*dy + F[5]*dz;
    const float by = F[6]*dx + F[7]*dy + F[8]*dz;
    const float bz = F[9]*dx + F[10]*dy + F[11]*dz;

    float t0 = tmn, t1 = tmx;
    #pragma unroll
    for (int ax3 = 0; ax3 < 3; ax3++) {
        float a = (ax3 == 0) ? ax : (ax3 == 1) ? ay : az;
        float b = (ax3 == 0) ? bx : (ax3 == 1) ? by : bz;
        if (fabsf(b) > 1e-9f) {
            float inv = 1.0f / b;
            float l = (-1.0f - a) * inv;
            float hgh = (1.0f - a) * inv;
            t0 = fmaxf(t0, fminf(l, hgh));
            t1 = fminf(t1, fmaxf(l, hgh));
        } else if (fabsf(a) >= 1.0f) {
            t1 = -1e30f;
        }
    }
    int ilo = (int)ceilf((t0 - tmn) * INV_DT - 0.51f);
    int ihi = (int)floorf((t1 - tmn) * INV_DT - 0.49f);
    ilo = max(ilo, (int)blockIdx.z * CHUNK);
    ihi = min(ihi, (int)blockIdx.z * CHUNK + CHUNK - 1);
    ihi = min(ihi, NSTEP - 1);
    if (ihi < ilo) return;

    const uint2* vk = g_vox + k * 4096;

    for (int i = ilo; i <= ihi; i++) {
        float t = tmn + ((float)i + 0.5f) * DT;
        float lx = fmaf(t, bx, ax);
        float ly = fmaf(t, by, ay);
        float lz = fmaf(t, bz, az);
        if (!(fabsf(lx) < 1.0f && fabsf(ly) < 1.0f && fabsf(lz) < 1.0f)) continue;

        // inside-check guarantees g in (0,15); only the int min guard is needed
        float gx = (lx + 1.0f) * 7.5f;
        float gy = (ly + 1.0f) * 7.5f;
        float gz = (lz + 1.0f) * 7.5f;
        int x0 = min((int)gx, 14);
        int y0 = min((int)gy, 14);
        int z0 = min((int)gz, 14);
        float fx = gx - (float)x0, fy = gy - (float)y0, fz = gz - (float)z0;

        const uint2* base = vk + ((z0*16 + y0)*16 + x0);
        uint2 u000 = base[0],   u001 = base[1];
        uint2 u010 = base[16],  u011 = base[17];
        uint2 u100 = base[256], u101 = base[257];
        uint2 u110 = base[272], u111 = base[273];

        float w0z = 1.f - fz, w0y = 1.f - fy, w0x = 1.f - fx;
        float w00 = w0z*w0y, w01 = w0z*fy, w10 = fz*w0y, w11 = fz*fy;
        float w000 = w00*w0x, w001 = w00*fx;
        float w010 = w01*w0x, w011 = w01*fx;
        float w100 = w10*w0x, w101 = w10*fx;
        float w110 = w11*w0x, w111 = w11*fx;

        float s0 = 0.f, s1 = 0.f, s2 = 0.f, s3 = 0.f;
        #define ACC(u, wgt) { \
            float2 c01 = __half22float2(*reinterpret_cast<const __half2*>(&(u).x)); \
            float2 c23 = __half22float2(*reinterpret_cast<const __half2*>(&(u).y)); \
            s0 = fmaf(c01.x, (wgt), s0); s1 = fmaf(c01.y, (wgt), s1); \
            s2 = fmaf(c23.x, (wgt), s2); s3 = fmaf(c23.y, (wgt), s3); }
        ACC(u000, w000) ACC(u001, w001) ACC(u010, w010) ACC(u011, w011)
        ACC(u100, w100) ACC(u101, w101) ACC(u110, w110) ACC(u111, w111)
        #undef ACC

        float* dst = (float*)&g_s[i * HW + r];
        asm volatile("red.global.add.v4.f32 [%0], {%1, %2, %3, %4};"
                     :: "l"(dst), "f"(s0), "f"(s1), "f"(s2), "f"(s3) : "memory");
    }
}

// ----------------------------------------------------------- composite ----
__global__ void __launch_bounds__(256)
composite_kernel(const float* __restrict__ tminmax,
                 const float* __restrict__ primpos, const float* __restrict__ primrot,
                 const float* __restrict__ primscale,
                 float* __restrict__ out, int out_size)
{
    __shared__ int sbb[4];
    const int tid = threadIdx.x;
    block_bbox(primpos, primrot, primscale, sbb, tid);

    const int r = blockIdx.x * 256 + tid;
    const int w = r & (Wd - 1), h = r >> 8;

    float crx = 0.f, cry = 0.f, crz = 0.f, alpha = 0.f;
    if (!(w < sbb[0] || w > sbb[1] || h < sbb[2] || h > sbb[3])) {
        const float tmn = tminmax[r*2+0], tmx = tminmax[r*2+1];
        #pragma unroll 8
        for (int i = 0; i < NSTEP; i++) {
            float4 s = g_s[i * HW + r];
            float t = tmn + ((float)i + 0.5f) * DT;
            float contrib = fminf(1.0f, fmaf(s.w, DT, alpha)) - alpha;
            if (!(t < tmx)) contrib = 0.0f;
            crx = fmaf(s.x, contrib, crx);
            cry = fmaf(s.y, contrib, cry);
            crz = fmaf(s.z, contrib, crz);
            alpha += contrib;
        }
    }

    if (out_size >= 8 * HW) {
        out[0*HW + r] = crx; out[1*HW + r] = cry; out[2*HW + r] = crz;
        out[3*HW + r] = alpha;
        out[4*HW + r] = crx; out[5*HW + r] = cry; out[6*HW + r] = crz;
        out[7*HW + r] = alpha;
    } else {
        out[0*HW + r] = crx; out[1*HW + r] = cry; out[2*HW + r] = crz;
        out[3*HW + r] = alpha;
    }
}

extern "C" void kernel_launch(void* const* d_in, const int* in_sizes, int n_in,
                              void* d_out, int out_size) {
    const float* raypos    = (const float*)d_in[0];
    const float* raydir    = (const float*)d_in[1];
    const float* tminmax   = (const float*)d_in[2];
    const float* primpos   = (const float*)d_in[3];
    const float* primrot   = (const float*)d_in[4];
    const float* primscale = (const float*)d_in[5];
    const float* primrgba  = (const float*)d_in[6];
    float* out = (float*)d_out;

    prep_kernel<<<TR_BLOCKS + 1 + ZERO_BLOCKS, 256>>>(primrgba, primpos, primrot, primscale);
    dim3 sgrid(MAX_SUBT, KP, STEP_CHUNKS);
    splat_kernel<<<sgrid, 64>>>(raypos, raydir, tminmax);
    composite_kernel<<<HW/256, 256>>>(tminmax, primpos, primrot, primscale, out, out_size);
}